// round 9
// baseline (speedup 1.0000x reference)
#include <cuda_runtime.h>
#include <cstdint>
#include <cstddef>

// CrossLevelAttention via tf32 mma.sync flash attention.
// CTA: 128 threads / 4 warps, BM=128 q rows (32/warp), BN=64 key tiles.
// Q RNA-rounded to tf32 (SCALE folded) in smem; per-tile S-phase is kk-outer
// with Q/K fragments via ldmatrix.x4. cp.async double-buffered K/V (raw fp32,
// MMA truncates). P RNA-rounded to tf32 (consistent with row sums).
// Per-level output accumulated into gmem (RMW).

#define NHEAD 16
#define DH 64
#define CDIM (NHEAD * DH)
#define BM 128
#define BN 64
#define QSTR 68
#define KSK 68
#define KSV 72
#define SCALE 0.125f
#define QFLO (BM * QSTR)
#define KFLO (BN * KSK)
#define VFLO (BN * KSV)

__device__ __forceinline__ uint32_t f2tf(float f) {
    uint32_t r;
    asm("cvt.rna.tf32.f32 %0, %1;" : "=r"(r) : "f"(f));
    return r;
}

__device__ __forceinline__ void mma_tf32(
    float& c0, float& c1, float& c2, float& c3,
    uint32_t a0, uint32_t a1, uint32_t a2, uint32_t a3,
    uint32_t b0, uint32_t b1)
{
    asm volatile(
        "mma.sync.aligned.m16n8k8.row.col.f32.tf32.tf32.f32 "
        "{%0,%1,%2,%3}, {%4,%5,%6,%7}, {%8,%9}, {%0,%1,%2,%3};"
        : "+f"(c0), "+f"(c1), "+f"(c2), "+f"(c3)
        : "r"(a0), "r"(a1), "r"(a2), "r"(a3), "r"(b0), "r"(b1));
}

__device__ __forceinline__ void ldsm4(
    uint32_t& r0, uint32_t& r1, uint32_t& r2, uint32_t& r3, uint32_t saddr)
{
    asm volatile("ldmatrix.sync.aligned.m8n8.x4.shared.b16 {%0,%1,%2,%3}, [%4];"
                 : "=r"(r0), "=r"(r1), "=r"(r2), "=r"(r3) : "r"(saddr));
}

__device__ __forceinline__ void cpasync16(void* sdst, const void* gsrc) {
    uint32_t s = (uint32_t)__cvta_generic_to_shared(sdst);
    asm volatile("cp.async.cg.shared.global [%0], [%1], 16;" :: "r"(s), "l"(gsrc));
}
#define CP_COMMIT() asm volatile("cp.async.commit_group;" ::: "memory")

__device__ __forceinline__ void prefetch_tile(
    const float* __restrict__ kb, const float* __restrict__ vb,
    int kt, float* sK, float* sV, int tid)
{
    #pragma unroll
    for (int it = 0; it < 8; it++) {
        int idx = it * 128 + tid;   // 1024 float4 slots (64 rows x 16)
        int row = idx >> 4;
        int c4  = idx & 15;
        cpasync16(sK + row * KSK + c4 * 4, kb + (size_t)(kt + row) * CDIM + c4 * 4);
        cpasync16(sV + row * KSV + c4 * 4, vb + (size_t)(kt + row) * CDIM + c4 * 4);
    }
}

// One level for this warp's 32 q rows; writes (FIRST) / RMW-adds result to out.
template <bool CAUSAL, bool FIRST>
__device__ __forceinline__ void attend_level(
    const float* __restrict__ kbase, const float* __restrict__ vbase,
    int n_keys, int qw0, int ln, int g, int c, int tid, float lw,
    uint32_t qAddr,   // per-lane ldmatrix addr into this warp's sQ rows
    uint32_t kAddr,   // per-lane ldmatrix addr into sK buffer 0
    float* sKd, float* sVd, float* __restrict__ outp)
{
    float o0[32], o1[32];
    #pragma unroll
    for (int i = 0; i < 32; i++) { o0[i] = 0.f; o1[i] = 0.f; }
    float rs0 = 0.f, rs1 = 0.f, rs2 = 0.f, rs3 = 0.f;
    const int r0 = qw0 + g;               // rows r0, +8, +16, +24
    const int ntile = n_keys / BN;
    const int qs0 = (ln & ~3) + (c >> 1);
    const int qs1 = qs0 + 2;
    const bool odd = (c & 1);

    prefetch_tile(kbase, vbase, 0, sKd, sVd, tid);
    CP_COMMIT();

    for (int t = 0; t < ntile; t++) {
        if (t + 1 < ntile) {
            prefetch_tile(kbase, vbase, (t + 1) * BN,
                          sKd + ((t + 1) & 1) * KFLO,
                          sVd + ((t + 1) & 1) * VFLO, tid);
            CP_COMMIT();
            asm volatile("cp.async.wait_group 1;" ::: "memory");
        } else {
            asm volatile("cp.async.wait_group 0;" ::: "memory");
        }
        __syncthreads();

        const uint32_t* uV = reinterpret_cast<const uint32_t*>(sVd + (t & 1) * VFLO);
        const uint32_t kA = kAddr + (uint32_t)((t & 1) * KFLO * 4);
        const int kt = t * BN;
        const bool dom = CAUSAL && (kt + BN > qw0);

        // ---- S-phase: all 8 slices, kk-outer; each frag feeds 4 MMAs ----
        float sa[64];
        #pragma unroll
        for (int i = 0; i < 64; i++) sa[i] = 0.f;
        #pragma unroll
        for (int kk = 0; kk < 8; kk++) {
            uint32_t qa0, qa1, qa2, qa3, qb0, qb1, qb2, qb3;
            ldsm4(qa0, qa1, qa2, qa3, qAddr + (uint32_t)(kk * 32));
            ldsm4(qb0, qb1, qb2, qb3, qAddr + (uint32_t)(16 * QSTR * 4 + kk * 32));
            #pragma unroll
            for (int sp = 0; sp < 4; sp++) {
                uint32_t k0, k1, k2, k3;
                ldsm4(k0, k1, k2, k3, kA + (uint32_t)(sp * 16 * KSK * 4 + kk * 32));
                mma_tf32(sa[(2*sp)*8+0], sa[(2*sp)*8+1], sa[(2*sp)*8+2], sa[(2*sp)*8+3],
                         qa0, qa1, qa2, qa3, k0, k1);
                mma_tf32(sa[(2*sp)*8+4], sa[(2*sp)*8+5], sa[(2*sp)*8+6], sa[(2*sp)*8+7],
                         qb0, qb1, qb2, qb3, k0, k1);
                mma_tf32(sa[(2*sp+1)*8+0], sa[(2*sp+1)*8+1], sa[(2*sp+1)*8+2], sa[(2*sp+1)*8+3],
                         qa0, qa1, qa2, qa3, k2, k3);
                mma_tf32(sa[(2*sp+1)*8+4], sa[(2*sp+1)*8+5], sa[(2*sp+1)*8+6], sa[(2*sp+1)*8+7],
                         qb0, qb1, qb2, qb3, k2, k3);
            }
        }

        // ---- softmax + PV per slice ----
        #pragma unroll
        for (int s = 0; s < 8; s++) {
            float p0, p1, p2, p3, p4, p5, p6, p7;
            if (dom) {
                int k0 = kt + s * 8 + 2 * c;
                p0 = (k0     > r0     ) ? 0.f : __expf(sa[s*8+0]);
                p1 = (k0 + 1 > r0     ) ? 0.f : __expf(sa[s*8+1]);
                p2 = (k0     > r0 + 8 ) ? 0.f : __expf(sa[s*8+2]);
                p3 = (k0 + 1 > r0 + 8 ) ? 0.f : __expf(sa[s*8+3]);
                p4 = (k0     > r0 + 16) ? 0.f : __expf(sa[s*8+4]);
                p5 = (k0 + 1 > r0 + 16) ? 0.f : __expf(sa[s*8+5]);
                p6 = (k0     > r0 + 24) ? 0.f : __expf(sa[s*8+6]);
                p7 = (k0 + 1 > r0 + 24) ? 0.f : __expf(sa[s*8+7]);
            } else {
                p0 = __expf(sa[s*8+0]); p1 = __expf(sa[s*8+1]);
                p2 = __expf(sa[s*8+2]); p3 = __expf(sa[s*8+3]);
                p4 = __expf(sa[s*8+4]); p5 = __expf(sa[s*8+5]);
                p6 = __expf(sa[s*8+6]); p7 = __expf(sa[s*8+7]);
            }
            // RNA-round p to tf32: rs and MMA see identical values (unbiased).
            uint32_t u0 = f2tf(p0), u1 = f2tf(p1), u2 = f2tf(p2), u3 = f2tf(p3);
            uint32_t u4 = f2tf(p4), u5 = f2tf(p5), u6 = f2tf(p6), u7 = f2tf(p7);
            rs0 += __uint_as_float(u0) + __uint_as_float(u1);
            rs1 += __uint_as_float(u2) + __uint_as_float(u3);
            rs2 += __uint_as_float(u4) + __uint_as_float(u5);
            rs3 += __uint_as_float(u6) + __uint_as_float(u7);

            // C-layout -> A-layout via quad shuffles (both 16-row tiles)
            uint32_t x00 = __shfl_sync(0xffffffffu, u0, qs0);
            uint32_t x10 = __shfl_sync(0xffffffffu, u1, qs0);
            uint32_t x01 = __shfl_sync(0xffffffffu, u0, qs1);
            uint32_t x11 = __shfl_sync(0xffffffffu, u1, qs1);
            uint32_t x20 = __shfl_sync(0xffffffffu, u2, qs0);
            uint32_t x30 = __shfl_sync(0xffffffffu, u3, qs0);
            uint32_t x21 = __shfl_sync(0xffffffffu, u2, qs1);
            uint32_t x31 = __shfl_sync(0xffffffffu, u3, qs1);
            uint32_t a0 = odd ? x10 : x00;
            uint32_t a2 = odd ? x11 : x01;
            uint32_t a1 = odd ? x30 : x20;
            uint32_t a3 = odd ? x31 : x21;
            uint32_t y00 = __shfl_sync(0xffffffffu, u4, qs0);
            uint32_t y10 = __shfl_sync(0xffffffffu, u5, qs0);
            uint32_t y01 = __shfl_sync(0xffffffffu, u4, qs1);
            uint32_t y11 = __shfl_sync(0xffffffffu, u5, qs1);
            uint32_t y20 = __shfl_sync(0xffffffffu, u6, qs0);
            uint32_t y30 = __shfl_sync(0xffffffffu, u7, qs0);
            uint32_t y21 = __shfl_sync(0xffffffffu, u6, qs1);
            uint32_t y31 = __shfl_sync(0xffffffffu, u7, qs1);
            uint32_t a4 = odd ? y10 : y00;
            uint32_t a6 = odd ? y11 : y01;
            uint32_t a5 = odd ? y30 : y20;
            uint32_t a7 = odd ? y31 : y21;

            // O += P_slice V_slice (V B-frags shared by both 16-row tiles)
            #pragma unroll
            for (int dt = 0; dt < 8; dt++) {
                uint32_t b0 = uV[(s * 8 + c) * KSV + dt * 8 + g];
                uint32_t b1 = uV[(s * 8 + c + 4) * KSV + dt * 8 + g];
                mma_tf32(o0[dt*4+0], o0[dt*4+1], o0[dt*4+2], o0[dt*4+3],
                         a0, a1, a2, a3, b0, b1);
                mma_tf32(o1[dt*4+0], o1[dt*4+1], o1[dt*4+2], o1[dt*4+3],
                         a4, a5, a6, a7, b0, b1);
            }
        }
        __syncthreads();  // all reads of tile t done before its buffer refills
    }

    // Reduce row sums across the quad.
    rs0 += __shfl_xor_sync(0xffffffffu, rs0, 1);
    rs0 += __shfl_xor_sync(0xffffffffu, rs0, 2);
    rs1 += __shfl_xor_sync(0xffffffffu, rs1, 1);
    rs1 += __shfl_xor_sync(0xffffffffu, rs1, 2);
    rs2 += __shfl_xor_sync(0xffffffffu, rs2, 1);
    rs2 += __shfl_xor_sync(0xffffffffu, rs2, 2);
    rs3 += __shfl_xor_sync(0xffffffffu, rs3, 1);
    rs3 += __shfl_xor_sync(0xffffffffu, rs3, 2);
    float inv0 = lw / rs0, inv1 = lw / rs1, inv2 = lw / rs2, inv3 = lw / rs3;

    #pragma unroll
    for (int dt = 0; dt < 8; dt++) {
        float2* d0 = reinterpret_cast<float2*>(outp + dt * 8 + 2 * c);
        float2* d1 = reinterpret_cast<float2*>(outp + 8  * CDIM + dt * 8 + 2 * c);
        float2* d2 = reinterpret_cast<float2*>(outp + 16 * CDIM + dt * 8 + 2 * c);
        float2* d3 = reinterpret_cast<float2*>(outp + 24 * CDIM + dt * 8 + 2 * c);
        float2 v0 = make_float2(o0[dt*4+0] * inv0, o0[dt*4+1] * inv0);
        float2 v1 = make_float2(o0[dt*4+2] * inv1, o0[dt*4+3] * inv1);
        float2 v2 = make_float2(o1[dt*4+0] * inv2, o1[dt*4+1] * inv2);
        float2 v3 = make_float2(o1[dt*4+2] * inv3, o1[dt*4+3] * inv3);
        if (FIRST) {
            *d0 = v0; *d1 = v1; *d2 = v2; *d3 = v3;
        } else {
            float2 e0 = *d0, e1 = *d1, e2 = *d2, e3 = *d3;
            e0.x += v0.x; e0.y += v0.y; *d0 = e0;
            e1.x += v1.x; e1.y += v1.y; *d1 = e1;
            e2.x += v2.x; e2.y += v2.y; *d2 = e2;
            e3.x += v3.x; e3.y += v3.y; *d3 = e3;
        }
    }
}

__global__ __launch_bounds__(128, 2)
void xlvl_attn_mma_kernel(
    const float* __restrict__ Q,
    const float* __restrict__ K0, const float* __restrict__ V0,
    const float* __restrict__ K1, const float* __restrict__ V1,
    const float* __restrict__ K2, const float* __restrict__ V2,
    const float* __restrict__ logits,
    float* __restrict__ out,
    int T, int T1, int T2)
{
    extern __shared__ __align__(16) float dynsmem[];
    float* sQ  = dynsmem;                       // 128 x 68 (tf32 bits)
    float* sKd = dynsmem + QFLO;                // 2 x 64 x 68
    float* sVd = dynsmem + QFLO + 2 * KFLO;     // 2 x 64 x 72

    const int qb  = (int)(gridDim.x - 1 - blockIdx.x);  // heavy blocks first
    const int h   = blockIdx.y;
    const int b   = blockIdx.z;
    const int tid = threadIdx.x;
    const int w   = tid >> 5;
    const int ln  = tid & 31;
    const int g   = ln >> 2;
    const int c   = ln & 3;
    const int q0  = qb * BM;
    const int qw0 = q0 + w * 32;

    // Preload Q tile [BM x DH]: RNA-round to tf32 with SCALE folded in.
    {
        const float* Qg = Q + ((size_t)(b * NHEAD + h) * T + q0) * DH;
        uint32_t* sQu = reinterpret_cast<uint32_t*>(sQ);
        #pragma unroll
        for (int it = 0; it < 16; it++) {
            int idx = it * 128 + tid;   // 2048 float4 slots (128 rows x 16)
            int row = idx >> 4;
            int c4  = idx & 15;
            float4 v = *reinterpret_cast<const float4*>(Qg + (size_t)row * DH + c4 * 4);
            uint4 qv = make_uint4(f2tf(v.x * SCALE), f2tf(v.y * SCALE),
                                  f2tf(v.z * SCALE), f2tf(v.w * SCALE));
            *reinterpret_cast<uint4*>(sQu + row * QSTR + c4 * 4) = qv;
        }
    }
    __syncthreads();

    // Per-lane ldmatrix addresses.
    // Q A-frag: lane row = ln&15, col-half = (ln&16)?+4:+0
    const uint32_t sQb = (uint32_t)__cvta_generic_to_shared(sQ);
    const uint32_t qAddr = sQb
        + (uint32_t)(((w * 32 + (ln & 15)) * QSTR + ((ln & 16) >> 2)) * 4);
    // K B-frag pairs: lane row = (ln&7)+((ln&16)>>1), col-half = (ln&8)?+4:+0
    const uint32_t sKb = (uint32_t)__cvta_generic_to_shared(sKd);
    const uint32_t kAddr = sKb
        + (uint32_t)((((ln & 7) + ((ln & 16) >> 1)) * KSK + ((ln & 8) >> 1)) * 4);

    float l0 = logits[0], l1 = logits[1], l2 = logits[2];
    float mx = fmaxf(l0, fmaxf(l1, l2));
    float e0 = __expf(l0 - mx), e1 = __expf(l1 - mx), e2 = __expf(l2 - mx);
    float winv = 1.0f / (e0 + e1 + e2);
    float w0 = e0 * winv, w1 = e1 * winv, w2 = e2 * winv;

    float* outp = out + ((size_t)b * T + qw0 + g) * CDIM + h * DH;

    attend_level<true, true>(K0 + (size_t)b * T  * CDIM + h * DH,
                             V0 + (size_t)b * T  * CDIM + h * DH,
                             q0 + BM, qw0, ln, g, c, tid, w0,
                             qAddr, kAddr, sKd, sVd, outp);
    attend_level<false, false>(K1 + (size_t)b * T1 * CDIM + h * DH,
                               V1 + (size_t)b * T1 * CDIM + h * DH,
                               T1, qw0, ln, g, c, tid, w1,
                               qAddr, kAddr, sKd, sVd, outp);
    attend_level<false, false>(K2 + (size_t)b * T2 * CDIM + h * DH,
                               V2 + (size_t)b * T2 * CDIM + h * DH,
                               T2, qw0, ln, g, c, tid, w2,
                               qAddr, kAddr, sKd, sVd, outp);
}

extern "C" void kernel_launch(void* const* d_in, const int* in_sizes, int n_in,
                              void* d_out, int out_size)
{
    const float* Q      = (const float*)d_in[0];
    const float* K0     = (const float*)d_in[1];
    const float* V0     = (const float*)d_in[2];
    const float* K1     = (const float*)d_in[3];
    const float* V1     = (const float*)d_in[4];
    const float* K2     = (const float*)d_in[5];
    const float* V2     = (const float*)d_in[6];
    const float* logits = (const float*)d_in[7];
    float* out          = (float*)d_out;

    const int B  = 2;
    const int T  = in_sizes[1] / (B * CDIM);
    const int T1 = in_sizes[3] / (B * CDIM);
    const int T2 = in_sizes[5] / (B * CDIM);

    const int smem = (QFLO + 2 * KFLO + 2 * VFLO) * (int)sizeof(float); // 106,496
    static bool configured = false;
    if (!configured) {
        cudaFuncSetAttribute(xlvl_attn_mma_kernel,
                             cudaFuncAttributeMaxDynamicSharedMemorySize, smem);
        configured = true;
    }

    dim3 grid(T / BM, NHEAD, B);
    xlvl_attn_mma_kernel<<<grid, 128, smem>>>(Q, K0, V0, K1, V1, K2, V2, logits,
                                              out, T, T1, T2);
}